// round 15
// baseline (speedup 1.0000x reference)
#include <cuda_runtime.h>
#include <cuda_fp16.h>
#include <cstdint>

#define N_POINTS   262144
#define N_LEVELS   16
#define TABLE_SIZE 524288
#define HASH_MASK  0x7FFFFu
#define P2 2654435761u
#define P3 805459861u

#define N_DENSE      8           // levels 0..7 are densified
#define TOTAL_QCELLS 1067888     // sum over l<8 of (r+1)*r*r
#define N_TILES      5530        // 16x16 yz-tiles over all dense sheets

// resolutions are deterministic: round(16 * 32^(l/15))
__constant__ int c_res[N_LEVELS] =
    {16, 20, 25, 32, 40, 51, 64, 81, 102, 128, 161, 203, 256, 323, 406, 512};

// quad-cell offsets for dense levels: cells_l = (r+1)*r*r, x slowest, z fastest
__constant__ unsigned int c_qoff[N_DENSE + 1] =
    {0u, 4352u, 12752u, 29002u, 62794u, 128394u, 263646u, 529886u, 1067888u};

// build-tile offsets: tiles_l = (r+1) * ceil(r/16)^2
__constant__ unsigned int c_toff[N_DENSE + 1] =
    {0u, 17u, 101u, 205u, 337u, 706u, 1538u, 2578u, 5530u};
__constant__ int c_ntyz[N_DENSE] = {1, 2, 2, 2, 3, 4, 4, 6};   // ceil(r/16)

// dense quad grid: cell (x,y,z) packs fp16 feats of corners
// (y,z),(y,z+1),(y+1,z),(y+1,z+1) at that x -> one 16B load
__device__ uint4 g_q[TOTAL_QCELLS];   // 17.1 MB static scratch

// --------------------------------------------------------------------------
// Build kernel: one block = one (level, x, 16x16 yz-tile). Gather the 17x17
// corner sheet into smem once (~1.13 gathers/cell), emit 256 packed cells
// with coalesced 16B stores. (R7-proven.)
__global__ __launch_bounds__(256)
void build_quad_kernel(const float* __restrict__ tables)
{
    __shared__ float2 s_c[17][18];   // [y][z], z-row padded

    const int bid = blockIdx.x;
    int l = 0;
    #pragma unroll
    for (int i = 1; i < N_DENSE; i++)
        if ((unsigned)bid >= c_toff[i]) l = i;

    const int t   = bid - (int)c_toff[l];
    const int r   = c_res[l];
    const int nt  = c_ntyz[l];
    const int x   = t / (nt * nt);
    const int rem = t % (nt * nt);
    const int ty0 = (rem / nt) * 16;
    const int tz0 = (rem % nt) * 16;

    const int cy = min(16, r - ty0);
    const int cz = min(16, r - tz0);
    const int ny = cy + 1, nz = cz + 1;

    const float2* __restrict__ tab =
        (const float2*)tables + (size_t)l * TABLE_SIZE;
    const unsigned int hx = (unsigned int)x;   // prime for x is 1

    const int tid = threadIdx.x;
    for (int c = tid; c < ny * nz; c += 256) {
        const int yy = c / nz, zz = c % nz;
        const unsigned int h = hx ^ ((unsigned int)(ty0 + yy) * P2)
                                  ^ ((unsigned int)(tz0 + zz) * P3);
        s_c[yy][zz] = __ldg(tab + (h & HASH_MASK));
    }
    __syncthreads();

    const int yl = tid >> 4, zl = tid & 15;
    if (yl < cy && zl < cz) {
        const float2 f00 = s_c[yl][zl],     f01 = s_c[yl][zl + 1];
        const float2 f10 = s_c[yl + 1][zl], f11 = s_c[yl + 1][zl + 1];

        __half2 h00 = __floats2half2_rn(f00.x, f00.y);
        __half2 h01 = __floats2half2_rn(f01.x, f01.y);
        __half2 h10 = __floats2half2_rn(f10.x, f10.y);
        __half2 h11 = __floats2half2_rn(f11.x, f11.y);

        uint4 q;
        q.x = *(unsigned int*)&h00;
        q.y = *(unsigned int*)&h01;
        q.z = *(unsigned int*)&h10;
        q.w = *(unsigned int*)&h11;

        const unsigned int idx = c_qoff[l]
            + ((unsigned int)(x * r + (ty0 + yl)) * (unsigned int)r)
            + (unsigned int)(tz0 + zl);
        g_q[idx] = q;
    }
}

// --------------------------------------------------------------------------
// Main kernel v2: thread = (point, l) handles BOTH level l (dense, 2 gathers)
// and level l+8 (hashed, 8 gathers) -> 10 independent loads in flight per
// thread, uniform warp-level load balance.
__global__ __launch_bounds__(256, 6)
void hashgrid_encode2_kernel(const float* __restrict__ xyz,
                             const float* __restrict__ tables,
                             float*       __restrict__ out)
{
    const int idx   = blockIdx.x * blockDim.x + threadIdx.x;
    const int l     = idx & 7;          // dense level; hashed level = l + 8
    const int point = idx >> 3;

    // 8 lanes of a point-group read the same xyz -> L1 broadcast
    const float px = __ldg(xyz + 3 * point + 0);
    const float py = __ldg(xyz + 3 * point + 1);
    const float pz = __ldg(xyz + 3 * point + 2);

    const float HI = (float)(1.0 - 1e-6);
    const float ux = fminf(fmaxf(px + 0.5f, 0.0f), HI);
    const float uy = fminf(fmaxf(py + 0.5f, 0.0f), HI);
    const float uz = fminf(fmaxf(pz + 0.5f, 0.0f), HI);

    // ---------------- dense level l: compute indices, issue loads ----------
    const int   resd  = c_res[l];
    const float resdf = (float)resd;
    float gxd = ux * resdf, gyd = uy * resdf, gzd = uz * resdf;
    float fxd = floorf(gxd), fyd = floorf(gyd), fzd = floorf(gzd);
    const uint32_t dix = (uint32_t)fxd, diy = (uint32_t)fyd, diz = (uint32_t)fzd;

    const unsigned int ru   = (unsigned int)resd;
    const unsigned int idxA = c_qoff[l] + (dix * ru + diy) * ru + diz;
    const unsigned int idxB = idxA + ru * ru;

    const uint4 qa = __ldg(g_q + idxA);
    const uint4 qb = __ldg(g_q + idxB);

    // ---------------- hashed level l+8: compute indices, issue loads -------
    const int   resh  = c_res[l + 8];
    const float reshf = (float)resh;
    float gxh = ux * reshf, gyh = uy * reshf, gzh = uz * reshf;
    float fxh = floorf(gxh), fyh = floorf(gyh), fzh = floorf(gzh);
    const uint32_t hix = (uint32_t)fxh, hiy = (uint32_t)fyh, hiz = (uint32_t)fzh;

    const uint32_t hx0 = hix,       hx1 = hix + 1u;
    const uint32_t hy0 = hiy * P2,  hy1 = hy0 + P2;
    const uint32_t hz0 = hiz * P3,  hz1 = hz0 + P3;

    const uint32_t i0 = (hx0 ^ hy0 ^ hz0) & HASH_MASK;
    const uint32_t i1 = (hx0 ^ hy0 ^ hz1) & HASH_MASK;
    const uint32_t i2 = (hx0 ^ hy1 ^ hz0) & HASH_MASK;
    const uint32_t i3 = (hx0 ^ hy1 ^ hz1) & HASH_MASK;
    const uint32_t i4 = (hx1 ^ hy0 ^ hz0) & HASH_MASK;
    const uint32_t i5 = (hx1 ^ hy0 ^ hz1) & HASH_MASK;
    const uint32_t i6 = (hx1 ^ hy1 ^ hz0) & HASH_MASK;
    const uint32_t i7 = (hx1 ^ hy1 ^ hz1) & HASH_MASK;

    const float2* __restrict__ tab =
        (const float2*)tables + (size_t)(l + 8) * TABLE_SIZE;

    const float2 f0 = __ldg(tab + i0);
    const float2 f1 = __ldg(tab + i1);
    const float2 f2 = __ldg(tab + i2);
    const float2 f3 = __ldg(tab + i3);
    const float2 f4 = __ldg(tab + i4);
    const float2 f5 = __ldg(tab + i5);
    const float2 f6 = __ldg(tab + i6);
    const float2 f7 = __ldg(tab + i7);

    // ---------------- weights (computed while loads are in flight) ---------
    float wxd1 = gxd - fxd, wyd1 = gyd - fyd, wzd1 = gzd - fzd;
    float wxd0 = 1.0f - wxd1, wyd0 = 1.0f - wyd1, wzd0 = 1.0f - wzd1;
    float wxh1 = gxh - fxh, wyh1 = gyh - fyh, wzh1 = gzh - fzh;
    float wxh0 = 1.0f - wxh1, wyh0 = 1.0f - wyh1, wzh0 = 1.0f - wzh1;

    // ---------------- hashed combine ----------------
    const float w0 = wxh0 * wyh0 * wzh0;
    const float w1 = wxh0 * wyh0 * wzh1;
    const float w2 = wxh0 * wyh1 * wzh0;
    const float w3 = wxh0 * wyh1 * wzh1;
    const float w4 = wxh1 * wyh0 * wzh0;
    const float w5 = wxh1 * wyh0 * wzh1;
    const float w6 = wxh1 * wyh1 * wzh0;
    const float w7 = wxh1 * wyh1 * wzh1;

    const float h0 = w0 * f0.x + w1 * f1.x + w2 * f2.x + w3 * f3.x
                   + w4 * f4.x + w5 * f5.x + w6 * f6.x + w7 * f7.x;
    const float h1 = w0 * f0.y + w1 * f1.y + w2 * f2.y + w3 * f3.y
                   + w4 * f4.y + w5 * f5.y + w6 * f6.y + w7 * f7.y;

    // ---------------- dense combine ----------------
    const float2 a00 = __half22float2(*(const __half2*)&qa.x);
    const float2 a01 = __half22float2(*(const __half2*)&qa.y);
    const float2 a10 = __half22float2(*(const __half2*)&qa.z);
    const float2 a11 = __half22float2(*(const __half2*)&qa.w);
    const float2 b00 = __half22float2(*(const __half2*)&qb.x);
    const float2 b01 = __half22float2(*(const __half2*)&qb.y);
    const float2 b10 = __half22float2(*(const __half2*)&qb.z);
    const float2 b11 = __half22float2(*(const __half2*)&qb.w);

    const float w000 = wxd0 * wyd0 * wzd0, w001 = wxd0 * wyd0 * wzd1;
    const float w010 = wxd0 * wyd1 * wzd0, w011 = wxd0 * wyd1 * wzd1;
    const float w100 = wxd1 * wyd0 * wzd0, w101 = wxd1 * wyd0 * wzd1;
    const float w110 = wxd1 * wyd1 * wzd0, w111 = wxd1 * wyd1 * wzd1;

    const float d0 = w000 * a00.x + w001 * a01.x + w010 * a10.x + w011 * a11.x
                   + w100 * b00.x + w101 * b01.x + w110 * b10.x + w111 * b11.x;
    const float d1 = w000 * a00.y + w001 * a01.y + w010 * a10.y + w011 * a11.y
                   + w100 * b00.y + w101 * b01.y + w110 * b10.y + w111 * b11.y;

    // stores: 8 lanes cover slots l (first 64B) and l+8 (second 64B) of the
    // point's 128B output row
    float2* __restrict__ outv = (float2*)out;
    outv[(size_t)point * N_LEVELS + l]     = make_float2(d0, d1);
    outv[(size_t)point * N_LEVELS + l + 8] = make_float2(h0, h1);
}

// --------------------------------------------------------------------------
extern "C" void kernel_launch(void* const* d_in, const int* in_sizes, int n_in,
                              void* d_out, int out_size)
{
    const float* xyz    = (const float*)d_in[0];
    const float* tables = (const float*)d_in[1];
    float*       out    = (float*)d_out;

    build_quad_kernel<<<N_TILES, 256>>>(tables);

    const int total = N_POINTS * N_DENSE;   // 2,097,152 threads
    hashgrid_encode2_kernel<<<total / 256, 256>>>(xyz, tables, out);
}

// round 16
// speedup vs baseline: 1.3217x; 1.3217x over previous
#include <cuda_runtime.h>
#include <cuda_fp16.h>
#include <cstdint>

#define N_POINTS   262144
#define N_LEVELS   16
#define TABLE_SIZE 524288
#define HASH_MASK  0x7FFFFu
#define P2 2654435761u
#define P3 805459861u

#define N_DENSE      8           // levels 0..7 are densified
#define TOTAL_QCELLS 1067888     // sum over l<8 of (r+1)*r*r
#define N_TILES      5530        // 16x16 yz-tiles over all dense sheets

// resolutions are deterministic: round(16 * 32^(l/15))
__constant__ int c_res[N_LEVELS] =
    {16, 20, 25, 32, 40, 51, 64, 81, 102, 128, 161, 203, 256, 323, 406, 512};

// quad-cell offsets for dense levels: cells_l = (r+1)*r*r, x slowest, z fastest
__constant__ unsigned int c_qoff[N_DENSE + 1] =
    {0u, 4352u, 12752u, 29002u, 62794u, 128394u, 263646u, 529886u, 1067888u};

// build-tile offsets: tiles_l = (r+1) * ceil(r/16)^2
__constant__ unsigned int c_toff[N_DENSE + 1] =
    {0u, 17u, 101u, 205u, 337u, 706u, 1538u, 2578u, 5530u};
__constant__ int c_ntyz[N_DENSE] = {1, 2, 2, 2, 3, 4, 4, 6};   // ceil(r/16)

// dense quad grid: cell (x,y,z) packs fp16 feats of corners
// (y,z),(y,z+1),(y+1,z),(y+1,z+1) at that x -> one 16B load
__device__ uint4 g_q[TOTAL_QCELLS];   // 17.1 MB static scratch

// --------------------------------------------------------------------------
// Build kernel (R7-proven): one block = one (level, x, 16x16 yz-tile).
__global__ __launch_bounds__(256)
void build_quad_kernel(const float* __restrict__ tables)
{
    __shared__ float2 s_c[17][18];   // [y][z], z-row padded

    const int bid = blockIdx.x;
    int l = 0;
    #pragma unroll
    for (int i = 1; i < N_DENSE; i++)
        if ((unsigned)bid >= c_toff[i]) l = i;

    const int t   = bid - (int)c_toff[l];
    const int r   = c_res[l];
    const int nt  = c_ntyz[l];
    const int x   = t / (nt * nt);
    const int rem = t % (nt * nt);
    const int ty0 = (rem / nt) * 16;
    const int tz0 = (rem % nt) * 16;

    const int cy = min(16, r - ty0);
    const int cz = min(16, r - tz0);
    const int ny = cy + 1, nz = cz + 1;

    const float2* __restrict__ tab =
        (const float2*)tables + (size_t)l * TABLE_SIZE;
    const unsigned int hx = (unsigned int)x;   // prime for x is 1

    const int tid = threadIdx.x;
    for (int c = tid; c < ny * nz; c += 256) {
        const int yy = c / nz, zz = c % nz;
        const unsigned int h = hx ^ ((unsigned int)(ty0 + yy) * P2)
                                  ^ ((unsigned int)(tz0 + zz) * P3);
        s_c[yy][zz] = __ldg(tab + (h & HASH_MASK));
    }
    __syncthreads();

    const int yl = tid >> 4, zl = tid & 15;
    if (yl < cy && zl < cz) {
        const float2 f00 = s_c[yl][zl],     f01 = s_c[yl][zl + 1];
        const float2 f10 = s_c[yl + 1][zl], f11 = s_c[yl + 1][zl + 1];

        __half2 h00 = __floats2half2_rn(f00.x, f00.y);
        __half2 h01 = __floats2half2_rn(f01.x, f01.y);
        __half2 h10 = __floats2half2_rn(f10.x, f10.y);
        __half2 h11 = __floats2half2_rn(f11.x, f11.y);

        uint4 q;
        q.x = *(unsigned int*)&h00;
        q.y = *(unsigned int*)&h01;
        q.z = *(unsigned int*)&h10;
        q.w = *(unsigned int*)&h11;

        const unsigned int idx = c_qoff[l]
            + ((unsigned int)(x * r + (ty0 + yl)) * (unsigned int)r)
            + (unsigned int)(tz0 + zl);
        g_q[idx] = q;
    }
}

// --------------------------------------------------------------------------
// Main kernel: R7 layout (thread = (point, level), 16 lanes per point), but
// the 3 xyz loads per thread are replaced by 1 predicated load + 3 shuffles
// per warp: lanes 0..5 load the 6 floats of the warp's 2 points, then all
// lanes pick their components via __shfl_sync. Cuts the kernel's memory-
// instruction count by ~1/3 while leaving wavefront count unchanged.
__global__ __launch_bounds__(256, 8)
void hashgrid_encode_kernel(const float* __restrict__ xyz,
                            const float* __restrict__ tables,
                            float*       __restrict__ out)
{
    const int tid   = blockIdx.x * blockDim.x + threadIdx.x;
    const int level = tid & (N_LEVELS - 1);
    const int point = tid >> 4;

    // ---- xyz via warp shuffle: warp covers points p0, p0+1 ----
    const int lane  = threadIdx.x & 31;
    const int group = lane >> 4;                 // 0 -> p0, 1 -> p0+1
    const int p0    = (tid & ~31) >> 4;          // first point of this warp

    float v = 0.0f;
    if (lane < 6) v = xyz[p0 * 3 + lane];        // 6 floats: 2 points x 3
    const float px = __shfl_sync(0xffffffffu, v, group * 3 + 0);
    const float py = __shfl_sync(0xffffffffu, v, group * 3 + 1);
    const float pz = __shfl_sync(0xffffffffu, v, group * 3 + 2);

    const int   res  = c_res[level];
    const float resf = (float)res;

    const float HI = (float)(1.0 - 1e-6);
    float ux = fminf(fmaxf(px + 0.5f, 0.0f), HI);
    float uy = fminf(fmaxf(py + 0.5f, 0.0f), HI);
    float uz = fminf(fmaxf(pz + 0.5f, 0.0f), HI);

    float gx = ux * resf, gy = uy * resf, gz = uz * resf;
    float fx = floorf(gx), fy = floorf(gy), fz = floorf(gz);
    float wx1 = gx - fx, wy1 = gy - fy, wz1 = gz - fz;
    float wx0 = 1.0f - wx1, wy0 = 1.0f - wy1, wz0 = 1.0f - wz1;

    uint32_t ix = (uint32_t)fx, iy = (uint32_t)fy, iz = (uint32_t)fz;

    float o0, o1;

    if (level < N_DENSE) {
        // dense path: 2 x 16B quad-cell gathers (x and x+1)
        const unsigned int ru   = (unsigned int)res;
        const unsigned int idxA = c_qoff[level] + (ix * ru + iy) * ru + iz;
        const unsigned int idxB = idxA + ru * ru;

        const uint4 qa = __ldg(g_q + idxA);
        const uint4 qb = __ldg(g_q + idxB);

        const float2 a00 = __half22float2(*(const __half2*)&qa.x);
        const float2 a01 = __half22float2(*(const __half2*)&qa.y);
        const float2 a10 = __half22float2(*(const __half2*)&qa.z);
        const float2 a11 = __half22float2(*(const __half2*)&qa.w);
        const float2 b00 = __half22float2(*(const __half2*)&qb.x);
        const float2 b01 = __half22float2(*(const __half2*)&qb.y);
        const float2 b10 = __half22float2(*(const __half2*)&qb.z);
        const float2 b11 = __half22float2(*(const __half2*)&qb.w);

        const float w000 = wx0 * wy0 * wz0, w001 = wx0 * wy0 * wz1;
        const float w010 = wx0 * wy1 * wz0, w011 = wx0 * wy1 * wz1;
        const float w100 = wx1 * wy0 * wz0, w101 = wx1 * wy0 * wz1;
        const float w110 = wx1 * wy1 * wz0, w111 = wx1 * wy1 * wz1;

        o0 = w000 * a00.x + w001 * a01.x + w010 * a10.x + w011 * a11.x
           + w100 * b00.x + w101 * b01.x + w110 * b10.x + w111 * b11.x;
        o1 = w000 * a00.y + w001 * a01.y + w010 * a10.y + w011 * a11.y
           + w100 * b00.y + w101 * b01.y + w110 * b10.y + w111 * b11.y;
    } else {
        // hashed path: 8 x float2 gathers
        uint32_t hx0 = ix,      hx1 = ix + 1u;
        uint32_t hy0 = iy * P2, hy1 = hy0 + P2;
        uint32_t hz0 = iz * P3, hz1 = hz0 + P3;

        uint32_t i0 = (hx0 ^ hy0 ^ hz0) & HASH_MASK;
        uint32_t i1 = (hx0 ^ hy0 ^ hz1) & HASH_MASK;
        uint32_t i2 = (hx0 ^ hy1 ^ hz0) & HASH_MASK;
        uint32_t i3 = (hx0 ^ hy1 ^ hz1) & HASH_MASK;
        uint32_t i4 = (hx1 ^ hy0 ^ hz0) & HASH_MASK;
        uint32_t i5 = (hx1 ^ hy0 ^ hz1) & HASH_MASK;
        uint32_t i6 = (hx1 ^ hy1 ^ hz0) & HASH_MASK;
        uint32_t i7 = (hx1 ^ hy1 ^ hz1) & HASH_MASK;

        const float2* __restrict__ tab =
            (const float2*)tables + (size_t)level * TABLE_SIZE;

        float2 f0 = __ldg(tab + i0);
        float2 f1 = __ldg(tab + i1);
        float2 f2 = __ldg(tab + i2);
        float2 f3 = __ldg(tab + i3);
        float2 f4 = __ldg(tab + i4);
        float2 f5 = __ldg(tab + i5);
        float2 f6 = __ldg(tab + i6);
        float2 f7 = __ldg(tab + i7);

        float w0 = wx0 * wy0 * wz0;
        float w1 = wx0 * wy0 * wz1;
        float w2 = wx0 * wy1 * wz0;
        float w3 = wx0 * wy1 * wz1;
        float w4 = wx1 * wy0 * wz0;
        float w5 = wx1 * wy0 * wz1;
        float w6 = wx1 * wy1 * wz0;
        float w7 = wx1 * wy1 * wz1;

        o0 = w0 * f0.x + w1 * f1.x + w2 * f2.x + w3 * f3.x
           + w4 * f4.x + w5 * f5.x + w6 * f6.x + w7 * f7.x;
        o1 = w0 * f0.y + w1 * f1.y + w2 * f2.y + w3 * f3.y
           + w4 * f4.y + w5 * f5.y + w6 * f6.y + w7 * f7.y;
    }

    // lanes (level 0..15) of one point cover a contiguous 128B span
    float2* __restrict__ outv = (float2*)out;
    outv[(size_t)point * N_LEVELS + level] = make_float2(o0, o1);
}

// --------------------------------------------------------------------------
extern "C" void kernel_launch(void* const* d_in, const int* in_sizes, int n_in,
                              void* d_out, int out_size)
{
    const float* xyz    = (const float*)d_in[0];
    const float* tables = (const float*)d_in[1];
    float*       out    = (float*)d_out;

    build_quad_kernel<<<N_TILES, 256>>>(tables);

    const int total = N_POINTS * N_LEVELS;
    hashgrid_encode_kernel<<<total / 256, 256>>>(xyz, tables, out);
}